// round 17
// baseline (speedup 1.0000x reference)
#include <cuda_runtime.h>
#include <cuda_bf16.h>

// ---------------------------------------------------------------------------
// LoongSpikeKernel via warp-level bf16 MMA (HMMA; plain-sm_103 target).
//
// K[h, l] = 2*Re( sum_n C_disc[h,n] * exp(dtA[h,n] * l) ),  l = 16*m + d:
//   D[m,d] = sum_n Wr[m,n]*Er[d,n] + (-Wi[m,n])*Ei[d,n]
//   W[m,n] = 2*C_disc[n] * r16[n]^m,  E[d,n] = r1[n]^d
// Split hi+lo bf16 -> 6 term-GEMMs m128 n16 k64 per h, f32 accum.
//
// R17 (on passing R16): SW128 swizzle instead of 144B padded rows ->
//   smem 83KB -> 72KB -> 3 CTAs/SM (was 2). Wave tail 216 -> 68 CTAs and
//   24 warps/SM for latency hiding (R16: occ 20.8%, issue 40%).
// ---------------------------------------------------------------------------

typedef unsigned int uint;

static constexpr int ATILE = 128 * 128;              // 16384 B per A tile
static constexpr int BTILE = 16 * 128;               // 2048 B per B tile
static constexpr int B_OFF = 4 * ATILE;              // 65536
static constexpr int SMEM_TOTAL = B_OFF + 4 * BTILE; // 73728

// fp32 two-term Cody-Waite reduction + fast sincos.
static __device__ __forceinline__ void sincos_cw(float x, float* s, float* c) {
    float k = rintf(x * 0.15915494309189535f);
    float r = fmaf(k, -6.28125f, x);
    r = fmaf(k, -1.9353071795864769e-3f, r);
    __sincosf(r, s, c);
}

static __device__ __forceinline__ uint smem_u32(const void* p) {
    uint r;
    asm("{ .reg .u64 t; cvta.to.shared.u64 t, %1; cvt.u32.u64 %0, t; }"
        : "=r"(r) : "l"(p));
    return r;
}

// SW128 swizzle: permute 16B chunks; conflict-free ldmatrix & row stores.
static __device__ __forceinline__ int swz(int o) { return o ^ ((o >> 3) & 0x70); }

// split-store: hi = bf16(x), lo = bf16(x - hi)
static __device__ __forceinline__ void st_pair(char* bhi, char* blo, int off, float x) {
    __nv_bfloat16 hb = __float2bfloat16_rn(x);
    *reinterpret_cast<__nv_bfloat16*>(bhi + off) = hb;
    *reinterpret_cast<__nv_bfloat16*>(blo + off) =
        __float2bfloat16_rn(x - __bfloat162float(hb));
}

static __device__ __forceinline__ void ldmA(uint addr, uint& a0, uint& a1,
                                            uint& a2, uint& a3) {
    asm volatile("ldmatrix.sync.aligned.m8n8.x4.shared.b16 {%0,%1,%2,%3}, [%4];"
                 : "=r"(a0), "=r"(a1), "=r"(a2), "=r"(a3) : "r"(addr));
}
static __device__ __forceinline__ void ldmB(uint addr, uint& b0, uint& b1) {
    asm volatile("ldmatrix.sync.aligned.m8n8.x2.shared.b16 {%0,%1}, [%2];"
                 : "=r"(b0), "=r"(b1) : "r"(addr));
}
static __device__ __forceinline__ void mma16816(float* c, uint a0, uint a1,
                                                uint a2, uint a3, uint b0, uint b1) {
    asm volatile(
        "mma.sync.aligned.m16n8k16.row.col.f32.bf16.bf16.f32 "
        "{%0,%1,%2,%3}, {%4,%5,%6,%7}, {%8,%9}, {%0,%1,%2,%3};"
        : "+f"(c[0]), "+f"(c[1]), "+f"(c[2]), "+f"(c[3])
        : "r"(a0), "r"(a1), "r"(a2), "r"(a3), "r"(b0), "r"(b1));
}

extern __shared__ char smem_dyn[];

__global__ __launch_bounds__(256) void loong_hmma(
    float* __restrict__ out,
    const float* __restrict__ C_real,
    const float* __restrict__ log_dt,
    const float* __restrict__ log_A_real,
    const float* __restrict__ A_imag,
    const float* __restrict__ omega_logit,
    const float* __restrict__ eta_logit,
    int NST, int L) {
    const float OMIN = 1e-6f, OMAX = 100.0f, EMIN = 1e-6f, EMAX = 10.0f;
    const int h    = blockIdx.x;
    const int tid  = threadIdx.x;
    const int n    = tid & 63;          // state
    const int role = tid >> 6;          // 0..3: W rows [32*role, 32*role+32)

    __shared__ float2 s_dtA[64];

    // ---- per-state constants (redundant across roles) ----
    const int mi = n / NST;
    const int gi = h * NST + (n - mi * NST);

    float dt    = expf(log_dt[h]);
    float omega = OMIN + (OMAX - OMIN) / (1.f + expf(-omega_logit[mi]));
    float eta   = EMIN + (EMAX - EMIN) / (1.f + expf(-eta_logit[mi]));
    float Are   = -expf(log_A_real[gi]);
    float Aim   = A_imag[gi];
    float Afr   = -omega + eta * Are;
    float Afi   = eta * Aim;
    float Cr    = eta * C_real[gi * 2 + 0];     // CH = 1
    float Ci    = eta * C_real[gi * 2 + 1];
    float dtAr  = Afr * dt;
    float dtAi  = Afi * dt;

    // C_disc = C * (exp(dtA) - 1) / (A_frac + 1e-8)   (small-|A| fallback)
    float er = expf(dtAr);
    float s1, c1; sincos_cw(dtAi, &s1, &c1);
    float nr = er * c1 - 1.f;
    float ni = er * s1;
    float ddr = Afr + 1e-8f, ddi = Afi;
    float inv = 1.f / (ddr * ddr + ddi * ddi);
    float qr  = (nr * ddr + ni * ddi) * inv;
    float qi  = (ni * ddr - nr * ddi) * inv;
    float Cdr = Cr * qr - Ci * qi;
    float Cdi = Cr * qi + Ci * qr;
    if (sqrtf(Afr * Afr + Afi * Afi) < 1e-6f) { Cdr = Cr * dt; Cdi = Ci * dt; }
    float C2r = 2.f * Cdr, C2i = 2.f * Cdi;

    if (tid < 64) s_dtA[tid] = make_float2(dtAr, dtAi);

    // r16 = exp(16*dtA)
    float e16 = __expf(16.f * dtAr);
    float s16, c16; sincos_cw(16.f * dtAi, &s16, &c16);
    float r16r = e16 * c16, r16i = e16 * s16;

    char* Wrh = smem_dyn;
    char* Wrl = smem_dyn + ATILE;
    char* Wih = smem_dyn + 2 * ATILE;   // holds -Wi
    char* Wil = smem_dyn + 3 * ATILE;
    char* Erh = smem_dyn + B_OFF;
    char* Erl = smem_dyn + B_OFF + BTILE;
    char* Eih = smem_dyn + B_OFF + 2 * BTILE;
    char* Eil = smem_dyn + B_OFF + 3 * BTILE;

    // ---- W chain: rows m = 32*role .. 32*role+31, column n ----
    float wr, wi;
    if (role == 0) { wr = C2r; wi = C2i; }
    else {
        float a = 512.f * (float)role;          // 16 * 32 * role
        float eS = __expf(a * dtAr);
        float sS, cS; sincos_cw(a * dtAi, &sS, &cS);
        float pr = eS * cS, pi = eS * sS;
        wr = C2r * pr - C2i * pi;
        wi = C2r * pi + C2i * pr;
    }
#pragma unroll 4
    for (int m = 32 * role; m < 32 * role + 32; m++) {
        int off = swz(m * 128 + n * 2);
        st_pair(Wrh, Wrl, off, wr);
        st_pair(Wih, Wil, off, -wi);
        float tr = wr * r16r - wi * r16i;
        wi = wr * r16i + wi * r16r;
        wr = tr;
    }
    __syncthreads();                             // s_dtA visible

    // ---- E tile: entry (d, n2) = exp(d * dtA);  4 entries per thread ----
    {
        const int d  = tid >> 4;                 // 0..15
        const int n0 = (tid & 15) * 4;
        const float df = (float)d;
#pragma unroll
        for (int j = 0; j < 4; j++) {
            int n2 = n0 + j;
            float2 a = s_dtA[n2];
            float ee = __expf(df * a.x);
            float ss, cc; sincos_cw(df * a.y, &ss, &cc);
            int off = swz(d * 128 + n2 * 2);
            st_pair(Erh, Erl, off, ee * cc);
            st_pair(Eih, Eil, off, ee * ss);
        }
    }
    __syncthreads();                             // all tiles ready

    // ---- GEMM: 8 warps x (16 rows x 16 cols), K=64, 6 terms ----
    const int lane = tid & 31;
    const int m0   = (tid >> 5) * 16;
    const uint base = smem_u32(smem_dyn);
    const int rowA   = (m0 + (lane & 15)) * 128;
    const int chunkA = (lane >> 4) << 4;
    const int rowB   = (lane & 7) * 128;
    const int chunkB = ((lane >> 3) & 1) << 4;

    float c0[4] = {0.f, 0.f, 0.f, 0.f};
    float cn[4] = {0.f, 0.f, 0.f, 0.f};
    const int ta[6] = {0, 0, 1, 2, 2, 3};        // Wrh,Wrh,Wrl,Wih,Wih,Wil
    const int tb[6] = {0, 1, 0, 2, 3, 2};        // Erh,Erl,Erh,Eih,Eil,Eih
#pragma unroll
    for (int t6 = 0; t6 < 6; t6++) {
        uint Ab = base + ta[t6] * ATILE;
        uint Bb = base + B_OFF + tb[t6] * BTILE;
#pragma unroll
        for (int k0 = 0; k0 < 64; k0 += 16) {
            uint a0, a1, a2, a3, b0, b1, b2, b3;
            ldmA(Ab + swz(rowA + chunkA + k0 * 2), a0, a1, a2, a3);
            ldmB(Bb + swz(rowB + chunkB + k0 * 2), b0, b1);              // d 0..7
            ldmB(Bb + swz(rowB + 8 * 128 + chunkB + k0 * 2), b2, b3);    // d 8..15
            mma16816(c0, a0, a1, a2, a3, b0, b1);
            mma16816(cn, a0, a1, a2, a3, b2, b3);
        }
    }

    // ---- store: D[r][c] -> out[h*L + 16*r + c] ----
    const int r0 = m0 + (lane >> 2);
    const int cc = (lane & 3) * 2;
    float* op = out + (size_t)h * L;
    *reinterpret_cast<float2*>(op + 16 * r0 + cc)           = make_float2(c0[0], c0[1]);
    *reinterpret_cast<float2*>(op + 16 * (r0 + 8) + cc)     = make_float2(c0[2], c0[3]);
    *reinterpret_cast<float2*>(op + 16 * r0 + 8 + cc)       = make_float2(cn[0], cn[1]);
    *reinterpret_cast<float2*>(op + 16 * (r0 + 8) + 8 + cc) = make_float2(cn[2], cn[3]);
}

// ---------------------------------------------------------------------------
extern "C" void kernel_launch(void* const* d_in, const int* in_sizes, int n_in,
                              void* d_out, int out_size) {
    const float* C_real      = (const float*)d_in[0];
    const float* log_dt      = (const float*)d_in[1];
    const float* log_A_real  = (const float*)d_in[2];
    const float* A_imag      = (const float*)d_in[3];
    const float* omega_logit = (const float*)d_in[4];
    const float* eta_logit   = (const float*)d_in[5];

    int H   = in_sizes[1];               // 512
    int NST = in_sizes[2] / H;           // 32
    int L   = out_size / H;              // 2048 = 128*16 (CH = 1)

    static bool attr_set = false;
    if (!attr_set) {
        cudaFuncSetAttribute(loong_hmma,
                             cudaFuncAttributeMaxDynamicSharedMemorySize,
                             SMEM_TOTAL);
        attr_set = true;
    }
    loong_hmma<<<H, 256, SMEM_TOTAL>>>((float*)d_out, C_real, log_dt,
                                       log_A_real, A_imag, omega_logit,
                                       eta_logit, NST, L);
}